// round 2
// baseline (speedup 1.0000x reference)
#include <cuda_runtime.h>
#include <cuda_bf16.h>
#include <cstdint>

// ===================== sizes =====================
#define LL 16384
#define HH 1024
#define H2 2048
#define CCH 128          // scan chunk length
#define GG  (LL/CCH)     // 128 chunks
#define EPS 1e-5f

__device__ __forceinline__ float sigm(float z) { return 1.f / (1.f + expf(-z)); }

// ===================== device scratch =====================
__device__ __nv_bfloat16 g_hid_h[(size_t)LL*HH];
__device__ __nv_bfloat16 g_hid_l[(size_t)LL*HH];
__device__ float         g_u[(size_t)LL*HH];
__device__ float         g_gate[(size_t)LL*HH];
__device__ __nv_bfloat16 g_st_h[(size_t)LL*HH];
__device__ __nv_bfloat16 g_st_l[(size_t)LL*HH];
__device__ float         g_y[(size_t)LL*HH];
__device__ __nv_bfloat16 g_h2_h[(size_t)LL*HH];
__device__ __nv_bfloat16 g_h2_l[(size_t)LL*HH];
__device__ __nv_bfloat16 g_ff1_h[(size_t)LL*H2];
__device__ __nv_bfloat16 g_ff1_l[(size_t)LL*H2];
__device__ __nv_bfloat16 g_Wug_h[(size_t)H2*HH];
__device__ __nv_bfloat16 g_Wug_l[(size_t)H2*HH];
__device__ __nv_bfloat16 g_Wout_h[(size_t)HH*HH];
__device__ __nv_bfloat16 g_Wout_l[(size_t)HH*HH];
__device__ __nv_bfloat16 g_Wff1_h[(size_t)H2*HH];
__device__ __nv_bfloat16 g_Wff1_l[(size_t)H2*HH];
__device__ __nv_bfloat16 g_Wff2_h[(size_t)HH*H2];
__device__ __nv_bfloat16 g_Wff2_l[(size_t)HH*H2];
__device__ float g_cf[GG*HH], g_cb[GG*HH], g_sinf[GG*HH], g_sinb[GG*HH];

// ===================== small kernels =====================

// transpose + bf16 split: src [K,N] fp32 row-major -> dst_hi/lo [N,K] bf16
__global__ void transpose_split_kernel(const float* __restrict__ src,
                                       __nv_bfloat16* __restrict__ dh,
                                       __nv_bfloat16* __restrict__ dl,
                                       int K, int N) {
    __shared__ float tile[32][33];
    int kb = blockIdx.y * 32, nb = blockIdx.x * 32;
    int tx = threadIdx.x, ty = threadIdx.y;   // 32 x 8
    #pragma unroll
    for (int i = ty; i < 32; i += 8)
        tile[i][tx] = src[(size_t)(kb + i) * N + nb + tx];
    __syncthreads();
    #pragma unroll
    for (int i = ty; i < 32; i += 8) {
        float v = tile[tx][i];                 // element (k=kb+tx, n=nb+i)
        __nv_bfloat16 h = __float2bfloat16(v);
        float r = v - __bfloat162float(h);
        size_t o = (size_t)(nb + i) * K + kb + tx;
        dh[o] = h;
        dl[o] = __float2bfloat16(r);
    }
}

// LayerNorm + bf16 split output. block = 256 threads, one row per block.
__global__ void ln_split_kernel(const float* __restrict__ x, const float* __restrict__ w,
                                const float* __restrict__ b,
                                __nv_bfloat16* __restrict__ oh, __nv_bfloat16* __restrict__ ol) {
    __shared__ float red[8];
    int row = blockIdx.x, tid = threadIdx.x;
    const float* xr = x + (size_t)row * HH;
    float v[4];
    float s = 0.f;
    #pragma unroll
    for (int i = 0; i < 4; i++) { v[i] = xr[tid + i*256]; s += v[i]; }
    #pragma unroll
    for (int o = 16; o; o >>= 1) s += __shfl_xor_sync(0xffffffffu, s, o);
    if ((tid & 31) == 0) red[tid >> 5] = s;
    __syncthreads();
    float tot = 0.f;
    #pragma unroll
    for (int i = 0; i < 8; i++) tot += red[i];
    float mean = tot * (1.f / HH);
    __syncthreads();
    float vs = 0.f;
    #pragma unroll
    for (int i = 0; i < 4; i++) { float d = v[i] - mean; vs += d * d; }
    #pragma unroll
    for (int o = 16; o; o >>= 1) vs += __shfl_xor_sync(0xffffffffu, vs, o);
    if ((tid & 31) == 0) red[tid >> 5] = vs;
    __syncthreads();
    float var = 0.f;
    #pragma unroll
    for (int i = 0; i < 8; i++) var += red[i];
    var *= (1.f / HH);
    float rstd = rsqrtf(var + EPS);
    #pragma unroll
    for (int i = 0; i < 4; i++) {
        int idx = tid + i*256;
        float val = (v[i] - mean) * rstd * w[idx] + b[idx];
        __nv_bfloat16 h = __float2bfloat16(val);
        size_t o = (size_t)row * HH + idx;
        oh[o] = h;
        ol[o] = __float2bfloat16(val - __bfloat162float(h));
    }
}

// scan pass1: per-chunk carries. grid (GG, HH/128), block 128.
__global__ void scan_p1_kernel(const float* __restrict__ u, const float* __restrict__ sd,
                               float* __restrict__ cf, float* __restrict__ cb) {
    extern __shared__ float sm1[];       // CCH * 128 floats
    int g = blockIdx.x;
    int tid = threadIdx.x;
    int c = blockIdx.y * 128 + tid;
    float d = sigm(sd[c]);
    const float* up = u + (size_t)g * CCH * HH + c;
    #pragma unroll 4
    for (int t = 0; t < CCH; t++) sm1[t*128 + tid] = up[(size_t)t * HH];
    __syncthreads();
    float sf = 0.f, sb = 0.f;
    #pragma unroll 4
    for (int t = 0; t < CCH; t++) sf = d * sf + sm1[t*128 + tid];
    #pragma unroll 4
    for (int t = CCH - 1; t >= 0; t--) sb = d * sb + sm1[t*128 + tid];
    cf[g*HH + c] = sf;
    cb[g*HH + c] = sb;
}

// scan pass2: cross-chunk exclusive scan. grid HH/256, block 256.
__global__ void scan_p2_kernel(const float* __restrict__ cf, const float* __restrict__ cb,
                               const float* __restrict__ sd,
                               float* __restrict__ sinf, float* __restrict__ sinb) {
    int c = blockIdx.x * 256 + threadIdx.x;
    float d = sigm(sd[c]);
    float dC = d;
    #pragma unroll
    for (int i = 0; i < 7; i++) dC *= dC;   // d^128
    float s = 0.f;
    for (int g = 0; g < GG; g++) { sinf[g*HH + c] = s; s = dC * s + cf[g*HH + c]; }
    s = 0.f;
    for (int g = GG - 1; g >= 0; g--) { sinb[g*HH + c] = s; s = dC * s + cb[g*HH + c]; }
}

// scan pass3: local scans + combine + gate + bf16 split. grid (GG, HH/128), block 128.
__global__ void scan_p3_kernel(const float* __restrict__ u, const float* __restrict__ gate,
                               const float* __restrict__ sd,
                               const float* __restrict__ sinf, const float* __restrict__ sinb,
                               __nv_bfloat16* __restrict__ oh, __nv_bfloat16* __restrict__ ol) {
    extern __shared__ float sm3[];       // 2 * CCH * 128 floats
    float* bu = sm3;
    float* bfv = sm3 + CCH*128;
    int g = blockIdx.x;
    int tid = threadIdx.x;
    int c = blockIdx.y * 128 + tid;
    const float* up = u + (size_t)g * CCH * HH + c;
    #pragma unroll 4
    for (int t = 0; t < CCH; t++) bu[t*128 + tid] = up[(size_t)t * HH];
    __syncthreads();
    float d = sigm(sd[c]);
    float s = sinf[g*HH + c];
    #pragma unroll 4
    for (int t = 0; t < CCH; t++) {
        s = d * s + bu[t*128 + tid];
        bfv[t*128 + tid] = s;
    }
    float sb = sinb[g*HH + c];
    const float* gp = gate + (size_t)g * CCH * HH + c;
    #pragma unroll 2
    for (int t = CCH - 1; t >= 0; t--) {
        sb = d * sb + bu[t*128 + tid];
        float so = 0.5f * (bfv[t*128 + tid] + sb) * gp[(size_t)t * HH];
        __nv_bfloat16 h = __float2bfloat16(so);
        size_t o = (size_t)(g*CCH + t) * HH + c;
        oh[o] = h;
        ol[o] = __float2bfloat16(so - __bfloat162float(h));
    }
}

// ===================== GEMM (bf16x3 split, mma.sync + cp.async) =====================
// C[M,N] = A[M,K] * B^T  (B stored [N,K]), fp32 accumulate.
// BM=128, BN=128, BK=32, 256 threads (8 warps: 2x4, warp tile 64x32), 3-stage cp.async.
// Epilogue MODE:
//  0: fused u/gate (n<HH: u=acc+bias0 -> out0 ; else gate=sigmoid(acc+bias1) -> out1)
//  1: y = res + acc + bias0 -> out0
//  2: silu(acc+bias0) -> split store oh/ol (row width H2)
//  3: out0 = res + acc + bias0
#define BKK 32
#define GSTAGES 3
#define GTHREADS 256
#define TILE_B 8192                 // 128 rows x 32 cols x 2B
#define STAGE_B (4*TILE_B)          // Ah, Al, Bh, Bl
#define GSMEM_BYTES (GSTAGES*STAGE_B)   // 98304

__device__ __forceinline__ uint32_t sw_off(int row, int chunk) {
    // tile: 128 rows x 64B, 16B chunks XOR-swizzled -> conflict-free for
    // cp.async 16B stores and ldmatrix 8x(16B) reads
    return (uint32_t)(row * 64 + ((chunk ^ ((row >> 1) & 3)) << 4));
}
__device__ __forceinline__ uint32_t smem_u32(const void* p) {
    uint32_t a;
    asm("{ .reg .u64 t; cvta.to.shared.u64 t, %1; cvt.u32.u64 %0, t; }" : "=r"(a) : "l"(p));
    return a;
}
__device__ __forceinline__ void cp16(uint32_t saddr, const void* gaddr) {
    asm volatile("cp.async.cg.shared.global [%0], [%1], 16;" :: "r"(saddr), "l"(gaddr));
}
#define CP_COMMIT() asm volatile("cp.async.commit_group;" ::: "memory")
#define CP_WAIT(n)  asm volatile("cp.async.wait_group %0;" :: "n"(n) : "memory")

__device__ __forceinline__ void ldsm4(uint32_t& r0, uint32_t& r1, uint32_t& r2, uint32_t& r3,
                                      uint32_t addr) {
    asm volatile("ldmatrix.sync.aligned.m8n8.x4.shared.b16 {%0,%1,%2,%3}, [%4];"
                 : "=r"(r0), "=r"(r1), "=r"(r2), "=r"(r3) : "r"(addr));
}
__device__ __forceinline__ void mma16816(float* c, const uint32_t* a, const uint32_t* b) {
    asm volatile("mma.sync.aligned.m16n8k16.row.col.f32.bf16.bf16.f32 "
                 "{%0,%1,%2,%3}, {%4,%5,%6,%7}, {%8,%9}, {%0,%1,%2,%3};"
                 : "+f"(c[0]), "+f"(c[1]), "+f"(c[2]), "+f"(c[3])
                 : "r"(a[0]), "r"(a[1]), "r"(a[2]), "r"(a[3]), "r"(b[0]), "r"(b[1]));
}

__device__ __forceinline__ void issue_stage(uint32_t sbase,
    const __nv_bfloat16* __restrict__ Ah, const __nv_bfloat16* __restrict__ Al,
    const __nv_bfloat16* __restrict__ Bh, const __nv_bfloat16* __restrict__ Bl,
    int m0, int n0, int K, int kbase, int tid)
{
    #pragma unroll
    for (int half = 0; half < 2; half++) {
        int v = tid + half * 256;              // 0..511 : 128 rows x 4 chunks
        int row = v >> 2, c = v & 3;
        uint32_t so = sw_off(row, c);
        size_t goA = (size_t)(m0 + row) * K + kbase + c * 8;
        size_t goB = (size_t)(n0 + row) * K + kbase + c * 8;
        cp16(sbase + 0*TILE_B + so, Ah + goA);
        cp16(sbase + 1*TILE_B + so, Al + goA);
        cp16(sbase + 2*TILE_B + so, Bh + goB);
        cp16(sbase + 3*TILE_B + so, Bl + goB);
    }
}

template <int MODE>
__device__ __forceinline__ void epi_pair(int r, int c, float v0, float v1,
    const float* __restrict__ bias0, const float* __restrict__ bias1,
    const float* __restrict__ res, float* __restrict__ out0, float* __restrict__ out1,
    __nv_bfloat16* __restrict__ oh, __nv_bfloat16* __restrict__ ol)
{
    size_t mg = (size_t)r;
    if (MODE == 0) {
        if (c < HH) {
            float2 o = make_float2(v0 + bias0[c], v1 + bias0[c+1]);
            *reinterpret_cast<float2*>(out0 + mg*HH + c) = o;
        } else {
            int cc = c - HH;
            float2 o = make_float2(sigm(v0 + bias1[cc]), sigm(v1 + bias1[cc+1]));
            *reinterpret_cast<float2*>(out1 + mg*HH + cc) = o;
        }
    } else if (MODE == 1 || MODE == 3) {
        float2 rr = *reinterpret_cast<const float2*>(res + mg*HH + c);
        float2 o = make_float2(rr.x + v0 + bias0[c], rr.y + v1 + bias0[c+1]);
        *reinterpret_cast<float2*>(out0 + mg*HH + c) = o;
    } else { // MODE 2: silu + bf16 split
        float t0 = v0 + bias0[c], t1 = v1 + bias0[c+1];
        float s0 = t0 * sigm(t0), s1 = t1 * sigm(t1);
        __nv_bfloat16 h0 = __float2bfloat16(s0), h1 = __float2bfloat16(s1);
        __nv_bfloat162 ph; ph.x = h0; ph.y = h1;
        __nv_bfloat162 pl;
        pl.x = __float2bfloat16(s0 - __bfloat162float(h0));
        pl.y = __float2bfloat16(s1 - __bfloat162float(h1));
        *reinterpret_cast<__nv_bfloat162*>(oh + mg*H2 + c) = ph;
        *reinterpret_cast<__nv_bfloat162*>(ol + mg*H2 + c) = pl;
    }
}

template <int MODE>
__global__ void __launch_bounds__(GTHREADS, 2) gemm_bf16x3_kernel(
    const __nv_bfloat16* __restrict__ Ah, const __nv_bfloat16* __restrict__ Al, int K,
    const __nv_bfloat16* __restrict__ Bh, const __nv_bfloat16* __restrict__ Bl,
    const float* __restrict__ bias0, const float* __restrict__ bias1,
    const float* __restrict__ res, float* __restrict__ out0, float* __restrict__ out1,
    __nv_bfloat16* __restrict__ oh, __nv_bfloat16* __restrict__ ol)
{
    extern __shared__ char smem[];
    uint32_t sb = smem_u32(smem);
    const int tid = threadIdx.x, wid = tid >> 5, lid = tid & 31;
    const int m0 = blockIdx.x * 128, n0 = blockIdx.y * 128;
    const int wr = wid >> 2, wc = wid & 3;       // warp tile: rows wr*64, cols wc*32
    const int nk = K >> 5;

    float acc[4][4][4];
    #pragma unroll
    for (int i = 0; i < 4; i++)
        #pragma unroll
        for (int j = 0; j < 4; j++)
            #pragma unroll
            for (int q = 0; q < 4; q++) acc[i][j][q] = 0.f;

    // prologue
    #pragma unroll
    for (int s = 0; s < GSTAGES - 1; s++) {
        issue_stage(sb + s*STAGE_B, Ah, Al, Bh, Bl, m0, n0, K, s*BKK, tid);
        CP_COMMIT();
    }

    for (int kc = 0; kc < nk; kc++) {
        CP_WAIT(GSTAGES - 2);
        __syncthreads();
        uint32_t st = sb + (uint32_t)(kc % GSTAGES) * STAGE_B;
        uint32_t sAh = st, sAl = st + TILE_B, sBh = st + 2*TILE_B, sBl = st + 3*TILE_B;

        #pragma unroll
        for (int kt = 0; kt < 2; kt++) {
            uint32_t ah[4][4], al[4][4], bh[4][2], bl[4][2];
            #pragma unroll
            for (int mt = 0; mt < 4; mt++) {
                int row = wr*64 + mt*16 + ((lid >> 3) & 1) * 8 + (lid & 7);
                int ch  = kt*2 + (lid >> 4);
                uint32_t off = sw_off(row, ch);
                ldsm4(ah[mt][0], ah[mt][1], ah[mt][2], ah[mt][3], sAh + off);
                ldsm4(al[mt][0], al[mt][1], al[mt][2], al[mt][3], sAl + off);
            }
            #pragma unroll
            for (int np = 0; np < 2; np++) {
                int row = wc*32 + np*16 + (lid >> 4) * 8 + (lid & 7);
                int ch  = kt*2 + ((lid >> 3) & 1);
                uint32_t off = sw_off(row, ch);
                uint32_t r0, r1, r2, r3;
                ldsm4(r0, r1, r2, r3, sBh + off);
                bh[np*2][0] = r0; bh[np*2][1] = r1; bh[np*2+1][0] = r2; bh[np*2+1][1] = r3;
                ldsm4(r0, r1, r2, r3, sBl + off);
                bl[np*2][0] = r0; bl[np*2][1] = r1; bl[np*2+1][0] = r2; bl[np*2+1][1] = r3;
            }
            #pragma unroll
            for (int mt = 0; mt < 4; mt++)
                #pragma unroll
                for (int nt = 0; nt < 4; nt++) {
                    mma16816(acc[mt][nt], ah[mt], bh[nt]);
                    mma16816(acc[mt][nt], al[mt], bh[nt]);
                    mma16816(acc[mt][nt], ah[mt], bl[nt]);
                }
        }
        __syncthreads();
        int next = kc + GSTAGES - 1;
        if (next < nk)
            issue_stage(sb + (uint32_t)(next % GSTAGES) * STAGE_B,
                        Ah, Al, Bh, Bl, m0, n0, K, next*BKK, tid);
        CP_COMMIT();
    }

    // epilogue: direct global stores (c-frag: lane l -> row l/4 (+8), cols 2*(l&3))
    #pragma unroll
    for (int mt = 0; mt < 4; mt++)
        #pragma unroll
        for (int nt = 0; nt < 4; nt++) {
            float* a4 = acc[mt][nt];
            int r = m0 + wr*64 + mt*16 + (lid >> 2);
            int c = n0 + wc*32 + nt*8 + ((lid & 3) << 1);
            epi_pair<MODE>(r,     c, a4[0], a4[1], bias0, bias1, res, out0, out1, oh, ol);
            epi_pair<MODE>(r + 8, c, a4[2], a4[3], bias0, bias1, res, out0, out1, oh, ol);
        }
}

// ===================== host =====================

extern "C" void kernel_launch(void* const* d_in, const int* in_sizes, int n_in,
                              void* d_out, int out_size) {
    const float* x        = (const float*)d_in[0];
    const float* ln1_w    = (const float*)d_in[1];
    const float* ln1_b    = (const float*)d_in[2];
    const float* W_in     = (const float*)d_in[3];
    const float* b_in     = (const float*)d_in[4];
    const float* W_gate   = (const float*)d_in[5];
    const float* b_gate   = (const float*)d_in[6];
    const float* W_out    = (const float*)d_in[7];
    const float* b_out    = (const float*)d_in[8];
    const float* sdecay   = (const float*)d_in[9];
    const float* ln2_w    = (const float*)d_in[10];
    const float* ln2_b    = (const float*)d_in[11];
    const float* W_ff1    = (const float*)d_in[12];
    const float* b_ff1    = (const float*)d_in[13];
    const float* W_ff2    = (const float*)d_in[14];
    const float* b_ff2    = (const float*)d_in[15];
    float* out = (float*)d_out;

    void *p_hid_h, *p_hid_l, *p_u, *p_gate, *p_st_h, *p_st_l, *p_y, *p_h2_h, *p_h2_l;
    void *p_ff1_h, *p_ff1_l;
    void *p_Wug_h, *p_Wug_l, *p_Wout_h, *p_Wout_l, *p_Wff1_h, *p_Wff1_l, *p_Wff2_h, *p_Wff2_l;
    void *p_cf, *p_cb, *p_sinf, *p_sinb;
    cudaGetSymbolAddress(&p_hid_h, g_hid_h);   cudaGetSymbolAddress(&p_hid_l, g_hid_l);
    cudaGetSymbolAddress(&p_u, g_u);           cudaGetSymbolAddress(&p_gate, g_gate);
    cudaGetSymbolAddress(&p_st_h, g_st_h);     cudaGetSymbolAddress(&p_st_l, g_st_l);
    cudaGetSymbolAddress(&p_y, g_y);
    cudaGetSymbolAddress(&p_h2_h, g_h2_h);     cudaGetSymbolAddress(&p_h2_l, g_h2_l);
    cudaGetSymbolAddress(&p_ff1_h, g_ff1_h);   cudaGetSymbolAddress(&p_ff1_l, g_ff1_l);
    cudaGetSymbolAddress(&p_Wug_h, g_Wug_h);   cudaGetSymbolAddress(&p_Wug_l, g_Wug_l);
    cudaGetSymbolAddress(&p_Wout_h, g_Wout_h); cudaGetSymbolAddress(&p_Wout_l, g_Wout_l);
    cudaGetSymbolAddress(&p_Wff1_h, g_Wff1_h); cudaGetSymbolAddress(&p_Wff1_l, g_Wff1_l);
    cudaGetSymbolAddress(&p_Wff2_h, g_Wff2_h); cudaGetSymbolAddress(&p_Wff2_l, g_Wff2_l);
    cudaGetSymbolAddress(&p_cf, g_cf);         cudaGetSymbolAddress(&p_cb, g_cb);
    cudaGetSymbolAddress(&p_sinf, g_sinf);     cudaGetSymbolAddress(&p_sinb, g_sinb);

    cudaFuncSetAttribute(gemm_bf16x3_kernel<0>, cudaFuncAttributeMaxDynamicSharedMemorySize, GSMEM_BYTES);
    cudaFuncSetAttribute(gemm_bf16x3_kernel<1>, cudaFuncAttributeMaxDynamicSharedMemorySize, GSMEM_BYTES);
    cudaFuncSetAttribute(gemm_bf16x3_kernel<2>, cudaFuncAttributeMaxDynamicSharedMemorySize, GSMEM_BYTES);
    cudaFuncSetAttribute(gemm_bf16x3_kernel<3>, cudaFuncAttributeMaxDynamicSharedMemorySize, GSMEM_BYTES);
    cudaFuncSetAttribute(scan_p1_kernel, cudaFuncAttributeMaxDynamicSharedMemorySize, CCH*128*4);
    cudaFuncSetAttribute(scan_p3_kernel, cudaFuncAttributeMaxDynamicSharedMemorySize, 2*CCH*128*4);

    dim3 tb(32, 8);
    // weight prep: transpose + split
    transpose_split_kernel<<<dim3(HH/32, HH/32), tb>>>(W_in,  (__nv_bfloat16*)p_Wug_h, (__nv_bfloat16*)p_Wug_l, HH, HH);
    transpose_split_kernel<<<dim3(HH/32, HH/32), tb>>>(W_gate, (__nv_bfloat16*)p_Wug_h + (size_t)HH*HH,
                                                        (__nv_bfloat16*)p_Wug_l + (size_t)HH*HH, HH, HH);
    transpose_split_kernel<<<dim3(HH/32, HH/32), tb>>>(W_out, (__nv_bfloat16*)p_Wout_h, (__nv_bfloat16*)p_Wout_l, HH, HH);
    transpose_split_kernel<<<dim3(H2/32, HH/32), tb>>>(W_ff1, (__nv_bfloat16*)p_Wff1_h, (__nv_bfloat16*)p_Wff1_l, HH, H2);
    transpose_split_kernel<<<dim3(HH/32, H2/32), tb>>>(W_ff2, (__nv_bfloat16*)p_Wff2_h, (__nv_bfloat16*)p_Wff2_l, H2, HH);

    // LN1 -> hidden (split)
    ln_split_kernel<<<LL, 256>>>(x, ln1_w, ln1_b, (__nv_bfloat16*)p_hid_h, (__nv_bfloat16*)p_hid_l);

    // G1: fused u / gate GEMM (N = 2048)
    gemm_bf16x3_kernel<0><<<dim3(LL/128, H2/128), GTHREADS, GSMEM_BYTES>>>(
        (const __nv_bfloat16*)p_hid_h, (const __nv_bfloat16*)p_hid_l, HH,
        (const __nv_bfloat16*)p_Wug_h, (const __nv_bfloat16*)p_Wug_l,
        b_in, b_gate, nullptr, (float*)p_u, (float*)p_gate, nullptr, nullptr);

    // scan
    scan_p1_kernel<<<dim3(GG, HH/128), 128, CCH*128*4>>>(
        (const float*)p_u, sdecay, (float*)p_cf, (float*)p_cb);
    scan_p2_kernel<<<HH/256, 256>>>(
        (const float*)p_cf, (const float*)p_cb, sdecay, (float*)p_sinf, (float*)p_sinb);
    scan_p3_kernel<<<dim3(GG, HH/128), 128, 2*CCH*128*4>>>(
        (const float*)p_u, (const float*)p_gate, sdecay,
        (const float*)p_sinf, (const float*)p_sinb,
        (__nv_bfloat16*)p_st_h, (__nv_bfloat16*)p_st_l);

    // G2: y = x + state@W_out + b_out
    gemm_bf16x3_kernel<1><<<dim3(LL/128, HH/128), GTHREADS, GSMEM_BYTES>>>(
        (const __nv_bfloat16*)p_st_h, (const __nv_bfloat16*)p_st_l, HH,
        (const __nv_bfloat16*)p_Wout_h, (const __nv_bfloat16*)p_Wout_l,
        b_out, nullptr, x, (float*)p_y, nullptr, nullptr, nullptr);

    // LN2 -> h (split)
    ln_split_kernel<<<LL, 256>>>((const float*)p_y, ln2_w, ln2_b,
                                 (__nv_bfloat16*)p_h2_h, (__nv_bfloat16*)p_h2_l);

    // G3: ff1 = silu(h@W_ff1 + b_ff1), split for next GEMM (N = 2048)
    gemm_bf16x3_kernel<2><<<dim3(LL/128, H2/128), GTHREADS, GSMEM_BYTES>>>(
        (const __nv_bfloat16*)p_h2_h, (const __nv_bfloat16*)p_h2_l, HH,
        (const __nv_bfloat16*)p_Wff1_h, (const __nv_bfloat16*)p_Wff1_l,
        b_ff1, nullptr, nullptr, nullptr, nullptr,
        (__nv_bfloat16*)p_ff1_h, (__nv_bfloat16*)p_ff1_l);

    // G4: out = y + ff1@W_ff2 + b_ff2  (K = 2048)
    gemm_bf16x3_kernel<3><<<dim3(LL/128, HH/128), GTHREADS, GSMEM_BYTES>>>(
        (const __nv_bfloat16*)p_ff1_h, (const __nv_bfloat16*)p_ff1_l, H2,
        (const __nv_bfloat16*)p_Wff2_h, (const __nv_bfloat16*)p_Wff2_l,
        b_ff2, nullptr, (const float*)p_y, out, nullptr, nullptr, nullptr);
}

// round 3
// speedup vs baseline: 1.0101x; 1.0101x over previous
#include <cuda_runtime.h>
#include <cuda_bf16.h>
#include <cstdint>

// ===================== sizes =====================
#define LL 16384
#define HH 1024
#define H2 2048
#define CCH 128          // scan chunk length
#define GG  (LL/CCH)     // 128 chunks
#define EPS 1e-5f

__device__ __forceinline__ float sigm(float z) { return 1.f / (1.f + expf(-z)); }

// ===================== device scratch =====================
__device__ __nv_bfloat16 g_hid_h[(size_t)LL*HH];
__device__ __nv_bfloat16 g_hid_l[(size_t)LL*HH];
__device__ float         g_u[(size_t)LL*HH];
__device__ float         g_gate[(size_t)LL*HH];
__device__ __nv_bfloat16 g_st_h[(size_t)LL*HH];
__device__ __nv_bfloat16 g_st_l[(size_t)LL*HH];
__device__ float         g_y[(size_t)LL*HH];
__device__ __nv_bfloat16 g_h2_h[(size_t)LL*HH];
__device__ __nv_bfloat16 g_h2_l[(size_t)LL*HH];
__device__ __nv_bfloat16 g_ff1_h[(size_t)LL*H2];
__device__ __nv_bfloat16 g_ff1_l[(size_t)LL*H2];
__device__ __nv_bfloat16 g_Wug_h[(size_t)H2*HH];
__device__ __nv_bfloat16 g_Wug_l[(size_t)H2*HH];
__device__ __nv_bfloat16 g_Wout_h[(size_t)HH*HH];
__device__ __nv_bfloat16 g_Wout_l[(size_t)HH*HH];
__device__ __nv_bfloat16 g_Wff1_h[(size_t)H2*HH];
__device__ __nv_bfloat16 g_Wff1_l[(size_t)H2*HH];
__device__ __nv_bfloat16 g_Wff2_h[(size_t)HH*H2];
__device__ __nv_bfloat16 g_Wff2_l[(size_t)HH*H2];
__device__ float g_cf[GG*HH], g_cb[GG*HH], g_sinf[GG*HH], g_sinb[GG*HH];

// ===================== small kernels =====================

// transpose + bf16 split: src [K,N] fp32 row-major -> dst_hi/lo [N,K] bf16
__global__ void transpose_split_kernel(const float* __restrict__ src,
                                       __nv_bfloat16* __restrict__ dh,
                                       __nv_bfloat16* __restrict__ dl,
                                       int K, int N) {
    __shared__ float tile[32][33];
    int kb = blockIdx.y * 32, nb = blockIdx.x * 32;
    int tx = threadIdx.x, ty = threadIdx.y;   // 32 x 8
    #pragma unroll
    for (int i = ty; i < 32; i += 8)
        tile[i][tx] = src[(size_t)(kb + i) * N + nb + tx];
    __syncthreads();
    #pragma unroll
    for (int i = ty; i < 32; i += 8) {
        float v = tile[tx][i];                 // element (k=kb+tx, n=nb+i)
        __nv_bfloat16 h = __float2bfloat16(v);
        float r = v - __bfloat162float(h);
        size_t o = (size_t)(nb + i) * K + kb + tx;
        dh[o] = h;
        dl[o] = __float2bfloat16(r);
    }
}

// LayerNorm + bf16 split output. block = 256 threads, one row per block.
__global__ void ln_split_kernel(const float* __restrict__ x, const float* __restrict__ w,
                                const float* __restrict__ b,
                                __nv_bfloat16* __restrict__ oh, __nv_bfloat16* __restrict__ ol) {
    __shared__ float red[8];
    int row = blockIdx.x, tid = threadIdx.x;
    const float* xr = x + (size_t)row * HH;
    float v[4];
    float s = 0.f;
    #pragma unroll
    for (int i = 0; i < 4; i++) { v[i] = xr[tid + i*256]; s += v[i]; }
    #pragma unroll
    for (int o = 16; o; o >>= 1) s += __shfl_xor_sync(0xffffffffu, s, o);
    if ((tid & 31) == 0) red[tid >> 5] = s;
    __syncthreads();
    float tot = 0.f;
    #pragma unroll
    for (int i = 0; i < 8; i++) tot += red[i];
    float mean = tot * (1.f / HH);
    __syncthreads();
    float vs = 0.f;
    #pragma unroll
    for (int i = 0; i < 4; i++) { float d = v[i] - mean; vs += d * d; }
    #pragma unroll
    for (int o = 16; o; o >>= 1) vs += __shfl_xor_sync(0xffffffffu, vs, o);
    if ((tid & 31) == 0) red[tid >> 5] = vs;
    __syncthreads();
    float var = 0.f;
    #pragma unroll
    for (int i = 0; i < 8; i++) var += red[i];
    var *= (1.f / HH);
    float rstd = rsqrtf(var + EPS);
    #pragma unroll
    for (int i = 0; i < 4; i++) {
        int idx = tid + i*256;
        float val = (v[i] - mean) * rstd * w[idx] + b[idx];
        __nv_bfloat16 h = __float2bfloat16(val);
        size_t o = (size_t)row * HH + idx;
        oh[o] = h;
        ol[o] = __float2bfloat16(val - __bfloat162float(h));
    }
}

// scan pass1: per-chunk carries. grid (GG, HH/128), block 128.
__global__ void scan_p1_kernel(const float* __restrict__ u, const float* __restrict__ sd,
                               float* __restrict__ cf, float* __restrict__ cb) {
    extern __shared__ float sm1[];       // CCH * 128 floats
    int g = blockIdx.x;
    int tid = threadIdx.x;
    int c = blockIdx.y * 128 + tid;
    float d = sigm(sd[c]);
    const float* up = u + (size_t)g * CCH * HH + c;
    #pragma unroll 4
    for (int t = 0; t < CCH; t++) sm1[t*128 + tid] = up[(size_t)t * HH];
    __syncthreads();
    float sf = 0.f, sb = 0.f;
    #pragma unroll 4
    for (int t = 0; t < CCH; t++) sf = d * sf + sm1[t*128 + tid];
    #pragma unroll 4
    for (int t = CCH - 1; t >= 0; t--) sb = d * sb + sm1[t*128 + tid];
    cf[g*HH + c] = sf;
    cb[g*HH + c] = sb;
}

// scan pass2: cross-chunk exclusive scan. grid HH/256, block 256.
__global__ void scan_p2_kernel(const float* __restrict__ cf, const float* __restrict__ cb,
                               const float* __restrict__ sd,
                               float* __restrict__ sinf, float* __restrict__ sinb) {
    int c = blockIdx.x * 256 + threadIdx.x;
    float d = sigm(sd[c]);
    float dC = d;
    #pragma unroll
    for (int i = 0; i < 7; i++) dC *= dC;   // d^128
    float s = 0.f;
    for (int g = 0; g < GG; g++) { sinf[g*HH + c] = s; s = dC * s + cf[g*HH + c]; }
    s = 0.f;
    for (int g = GG - 1; g >= 0; g--) { sinb[g*HH + c] = s; s = dC * s + cb[g*HH + c]; }
}

// scan pass3: local scans + combine + gate + bf16 split. grid (GG, HH/128), block 128.
__global__ void scan_p3_kernel(const float* __restrict__ u, const float* __restrict__ gate,
                               const float* __restrict__ sd,
                               const float* __restrict__ sinf, const float* __restrict__ sinb,
                               __nv_bfloat16* __restrict__ oh, __nv_bfloat16* __restrict__ ol) {
    extern __shared__ float sm3[];       // 2 * CCH * 128 floats
    float* bu = sm3;
    float* bfv = sm3 + CCH*128;
    int g = blockIdx.x;
    int tid = threadIdx.x;
    int c = blockIdx.y * 128 + tid;
    const float* up = u + (size_t)g * CCH * HH + c;
    #pragma unroll 4
    for (int t = 0; t < CCH; t++) bu[t*128 + tid] = up[(size_t)t * HH];
    __syncthreads();
    float d = sigm(sd[c]);
    float s = sinf[g*HH + c];
    #pragma unroll 4
    for (int t = 0; t < CCH; t++) {
        s = d * s + bu[t*128 + tid];
        bfv[t*128 + tid] = s;
    }
    float sb = sinb[g*HH + c];
    const float* gp = gate + (size_t)g * CCH * HH + c;
    #pragma unroll 2
    for (int t = CCH - 1; t >= 0; t--) {
        sb = d * sb + bu[t*128 + tid];
        float so = 0.5f * (bfv[t*128 + tid] + sb) * gp[(size_t)t * HH];
        __nv_bfloat16 h = __float2bfloat16(so);
        size_t o = (size_t)(g*CCH + t) * HH + c;
        oh[o] = h;
        ol[o] = __float2bfloat16(so - __bfloat162float(h));
    }
}

// ===================== GEMM (bf16x3 split, mma.sync + cp.async) =====================
// C[M,N] = A[M,K] * B^T  (B stored [N,K]), fp32 accumulate.
// BM=128, BN=128, BK=32, 256 threads (8 warps: 2x4, warp tile 64x32), 3-stage cp.async.
// Term-sequenced fragment use keeps live registers <= 128 (no spills @ 2 CTA/SM).
#define BKK 32
#define GSTAGES 3
#define GTHREADS 256
#define TILE_B 8192                 // 128 rows x 32 cols x 2B
#define STAGE_B (4*TILE_B)          // Ah, Al, Bh, Bl
#define GSMEM_BYTES (GSTAGES*STAGE_B)   // 98304

__device__ __forceinline__ uint32_t sw_off(int row, int chunk) {
    // tile: 128 rows x 64B, 16B chunks XOR-swizzled -> conflict-free for
    // cp.async 16B stores and ldmatrix 8x(16B) reads
    return (uint32_t)(row * 64 + ((chunk ^ ((row >> 1) & 3)) << 4));
}
__device__ __forceinline__ uint32_t smem_u32(const void* p) {
    uint32_t a;
    asm("{ .reg .u64 t; cvta.to.shared.u64 t, %1; cvt.u32.u64 %0, t; }" : "=r"(a) : "l"(p));
    return a;
}
__device__ __forceinline__ void cp16(uint32_t saddr, const void* gaddr) {
    asm volatile("cp.async.cg.shared.global [%0], [%1], 16;" :: "r"(saddr), "l"(gaddr));
}
#define CP_COMMIT() asm volatile("cp.async.commit_group;" ::: "memory")
#define CP_WAIT(n)  asm volatile("cp.async.wait_group %0;" :: "n"(n) : "memory")

__device__ __forceinline__ void ldsm4(uint32_t& r0, uint32_t& r1, uint32_t& r2, uint32_t& r3,
                                      uint32_t addr) {
    asm volatile("ldmatrix.sync.aligned.m8n8.x4.shared.b16 {%0,%1,%2,%3}, [%4];"
                 : "=r"(r0), "=r"(r1), "=r"(r2), "=r"(r3) : "r"(addr));
}
__device__ __forceinline__ void mma16816(float* c, const uint32_t* a, const uint32_t* b) {
    asm volatile("mma.sync.aligned.m16n8k16.row.col.f32.bf16.bf16.f32 "
                 "{%0,%1,%2,%3}, {%4,%5,%6,%7}, {%8,%9}, {%0,%1,%2,%3};"
                 : "+f"(c[0]), "+f"(c[1]), "+f"(c[2]), "+f"(c[3])
                 : "r"(a[0]), "r"(a[1]), "r"(a[2]), "r"(a[3]), "r"(b[0]), "r"(b[1]));
}

__device__ __forceinline__ void issue_stage(uint32_t sbase,
    const __nv_bfloat16* __restrict__ Ah, const __nv_bfloat16* __restrict__ Al,
    const __nv_bfloat16* __restrict__ Bh, const __nv_bfloat16* __restrict__ Bl,
    int m0, int n0, int K, int kbase, int tid)
{
    #pragma unroll
    for (int half = 0; half < 2; half++) {
        int v = tid + half * 256;              // 0..511 : 128 rows x 4 chunks
        int row = v >> 2, c = v & 3;
        uint32_t so = sw_off(row, c);
        size_t goA = (size_t)(m0 + row) * K + kbase + c * 8;
        size_t goB = (size_t)(n0 + row) * K + kbase + c * 8;
        cp16(sbase + 0*TILE_B + so, Ah + goA);
        cp16(sbase + 1*TILE_B + so, Al + goA);
        cp16(sbase + 2*TILE_B + so, Bh + goB);
        cp16(sbase + 3*TILE_B + so, Bl + goB);
    }
}

template <int MODE>
__device__ __forceinline__ void epi_pair(int r, int c, float v0, float v1,
    const float* __restrict__ bias0, const float* __restrict__ bias1,
    const float* __restrict__ res, float* __restrict__ out0, float* __restrict__ out1,
    __nv_bfloat16* __restrict__ oh, __nv_bfloat16* __restrict__ ol)
{
    size_t mg = (size_t)r;
    if (MODE == 0) {
        if (c < HH) {
            float2 o = make_float2(v0 + bias0[c], v1 + bias0[c+1]);
            *reinterpret_cast<float2*>(out0 + mg*HH + c) = o;
        } else {
            int cc = c - HH;
            float2 o = make_float2(sigm(v0 + bias1[cc]), sigm(v1 + bias1[cc+1]));
            *reinterpret_cast<float2*>(out1 + mg*HH + cc) = o;
        }
    } else if (MODE == 1 || MODE == 3) {
        float2 rr = *reinterpret_cast<const float2*>(res + mg*HH + c);
        float2 o = make_float2(rr.x + v0 + bias0[c], rr.y + v1 + bias0[c+1]);
        *reinterpret_cast<float2*>(out0 + mg*HH + c) = o;
    } else { // MODE 2: silu + bf16 split
        float t0 = v0 + bias0[c], t1 = v1 + bias0[c+1];
        float s0 = t0 * sigm(t0), s1 = t1 * sigm(t1);
        __nv_bfloat16 h0 = __float2bfloat16(s0), h1 = __float2bfloat16(s1);
        __nv_bfloat162 ph; ph.x = h0; ph.y = h1;
        __nv_bfloat162 pl;
        pl.x = __float2bfloat16(s0 - __bfloat162float(h0));
        pl.y = __float2bfloat16(s1 - __bfloat162float(h1));
        *reinterpret_cast<__nv_bfloat162*>(oh + mg*H2 + c) = ph;
        *reinterpret_cast<__nv_bfloat162*>(ol + mg*H2 + c) = pl;
    }
}

template <int MODE>
__global__ void __launch_bounds__(GTHREADS, 2) gemm_bf16x3_kernel(
    const __nv_bfloat16* __restrict__ Ah, const __nv_bfloat16* __restrict__ Al, int K,
    const __nv_bfloat16* __restrict__ Bh, const __nv_bfloat16* __restrict__ Bl,
    const float* __restrict__ bias0, const float* __restrict__ bias1,
    const float* __restrict__ res, float* __restrict__ out0, float* __restrict__ out1,
    __nv_bfloat16* __restrict__ oh, __nv_bfloat16* __restrict__ ol)
{
    extern __shared__ char smem[];
    uint32_t sb = smem_u32(smem);
    const int tid = threadIdx.x, wid = tid >> 5, lid = tid & 31;
    const int m0 = blockIdx.x * 128, n0 = blockIdx.y * 128;
    const int wr = wid >> 2, wc = wid & 3;       // warp tile: rows wr*64, cols wc*32
    const int nk = K >> 5;

    float acc[4][4][4];
    #pragma unroll
    for (int i = 0; i < 4; i++)
        #pragma unroll
        for (int j = 0; j < 4; j++)
            #pragma unroll
            for (int q = 0; q < 4; q++) acc[i][j][q] = 0.f;

    // k-invariant swizzled read offsets (relative to each tile base)
    uint32_t offA[2][4], offB[2];
    #pragma unroll
    for (int kt = 0; kt < 2; kt++) {
        #pragma unroll
        for (int mt = 0; mt < 4; mt++) {
            int row = wr*64 + mt*16 + ((lid >> 3) & 1) * 8 + (lid & 7);
            int ch  = kt*2 + (lid >> 4);
            offA[kt][mt] = sw_off(row, ch);
        }
        int rowB = wc*32 + (lid >> 4) * 8 + (lid & 7);   // np folded below (+16 per np)
        int chB  = kt*2 + ((lid >> 3) & 1);
        offB[kt] = sw_off(rowB, chB);
    }

    // prologue
    #pragma unroll
    for (int s = 0; s < GSTAGES - 1; s++) {
        issue_stage(sb + s*STAGE_B, Ah, Al, Bh, Bl, m0, n0, K, s*BKK, tid);
        CP_COMMIT();
    }

    for (int kc = 0; kc < nk; kc++) {
        CP_WAIT(GSTAGES - 2);
        __syncthreads();
        // refill the slot consumed at iteration kc-1 ( == (kc+2) % 3 )
        int next = kc + GSTAGES - 1;
        if (next < nk)
            issue_stage(sb + (uint32_t)(next % GSTAGES) * STAGE_B,
                        Ah, Al, Bh, Bl, m0, n0, K, next*BKK, tid);
        CP_COMMIT();

        uint32_t st = sb + (uint32_t)(kc % GSTAGES) * STAGE_B;
        uint32_t sAh = st, sAl = st + TILE_B, sBh = st + 2*TILE_B, sBl = st + 3*TILE_B;

        #pragma unroll
        for (int kt = 0; kt < 2; kt++) {
            uint32_t ah[4][4], xx[4][4], bb[4][2];
            // phase 1: ah * bh
            #pragma unroll
            for (int mt = 0; mt < 4; mt++)
                ldsm4(ah[mt][0], ah[mt][1], ah[mt][2], ah[mt][3], sAh + offA[kt][mt]);
            #pragma unroll
            for (int np = 0; np < 2; np++) {
                uint32_t r0, r1, r2, r3;
                ldsm4(r0, r1, r2, r3, sBh + offB[kt] + (uint32_t)(np * 16 * 64));
                bb[np*2][0] = r0; bb[np*2][1] = r1; bb[np*2+1][0] = r2; bb[np*2+1][1] = r3;
            }
            #pragma unroll
            for (int mt = 0; mt < 4; mt++)
                #pragma unroll
                for (int nt = 0; nt < 4; nt++)
                    mma16816(acc[mt][nt], ah[mt], bb[nt]);
            // phase 2: al * bh  (bb still holds bh)
            #pragma unroll
            for (int mt = 0; mt < 4; mt++)
                ldsm4(xx[mt][0], xx[mt][1], xx[mt][2], xx[mt][3], sAl + offA[kt][mt]);
            #pragma unroll
            for (int mt = 0; mt < 4; mt++)
                #pragma unroll
                for (int nt = 0; nt < 4; nt++)
                    mma16816(acc[mt][nt], xx[mt], bb[nt]);
            // phase 3: ah * bl  (overwrite bb with bl; xx dead)
            #pragma unroll
            for (int np = 0; np < 2; np++) {
                uint32_t r0, r1, r2, r3;
                ldsm4(r0, r1, r2, r3, sBl + offB[kt] + (uint32_t)(np * 16 * 64));
                bb[np*2][0] = r0; bb[np*2][1] = r1; bb[np*2+1][0] = r2; bb[np*2+1][1] = r3;
            }
            #pragma unroll
            for (int mt = 0; mt < 4; mt++)
                #pragma unroll
                for (int nt = 0; nt < 4; nt++)
                    mma16816(acc[mt][nt], ah[mt], bb[nt]);
        }
        __syncthreads();
    }

    // epilogue: direct global stores (c-frag: lane l -> row l/4 (+8), cols 2*(l&3))
    #pragma unroll
    for (int mt = 0; mt < 4; mt++)
        #pragma unroll
        for (int nt = 0; nt < 4; nt++) {
            float* a4 = acc[mt][nt];
            int r = m0 + wr*64 + mt*16 + (lid >> 2);
            int c = n0 + wc*32 + nt*8 + ((lid & 3) << 1);
            epi_pair<MODE>(r,     c, a4[0], a4[1], bias0, bias1, res, out0, out1, oh, ol);
            epi_pair<MODE>(r + 8, c, a4[2], a4[3], bias0, bias1, res, out0, out1, oh, ol);
        }
}

// ===================== host =====================

extern "C" void kernel_launch(void* const* d_in, const int* in_sizes, int n_in,
                              void* d_out, int out_size) {
    const float* x        = (const float*)d_in[0];
    const float* ln1_w    = (const float*)d_in[1];
    const float* ln1_b    = (const float*)d_in[2];
    const float* W_in     = (const float*)d_in[3];
    const float* b_in     = (const float*)d_in[4];
    const float* W_gate   = (const float*)d_in[5];
    const float* b_gate   = (const float*)d_in[6];
    const float* W_out    = (const float*)d_in[7];
    const float* b_out    = (const float*)d_in[8];
    const float* sdecay   = (const float*)d_in[9];
    const float* ln2_w    = (const float*)d_in[10];
    const float* ln2_b    = (const float*)d_in[11];
    const float* W_ff1    = (const float*)d_in[12];
    const float* b_ff1    = (const float*)d_in[13];
    const float* W_ff2    = (const float*)d_in[14];
    const float* b_ff2    = (const float*)d_in[15];
    float* out = (float*)d_out;

    void *p_hid_h, *p_hid_l, *p_u, *p_gate, *p_st_h, *p_st_l, *p_y, *p_h2_h, *p_h2_l;
    void *p_ff1_h, *p_ff1_l;
    void *p_Wug_h, *p_Wug_l, *p_Wout_h, *p_Wout_l, *p_Wff1_h, *p_Wff1_l, *p_Wff2_h, *p_Wff2_l;
    void *p_cf, *p_cb, *p_sinf, *p_sinb;
    cudaGetSymbolAddress(&p_hid_h, g_hid_h);   cudaGetSymbolAddress(&p_hid_l, g_hid_l);
    cudaGetSymbolAddress(&p_u, g_u);           cudaGetSymbolAddress(&p_gate, g_gate);
    cudaGetSymbolAddress(&p_st_h, g_st_h);     cudaGetSymbolAddress(&p_st_l, g_st_l);
    cudaGetSymbolAddress(&p_y, g_y);
    cudaGetSymbolAddress(&p_h2_h, g_h2_h);     cudaGetSymbolAddress(&p_h2_l, g_h2_l);
    cudaGetSymbolAddress(&p_ff1_h, g_ff1_h);   cudaGetSymbolAddress(&p_ff1_l, g_ff1_l);
    cudaGetSymbolAddress(&p_Wug_h, g_Wug_h);   cudaGetSymbolAddress(&p_Wug_l, g_Wug_l);
    cudaGetSymbolAddress(&p_Wout_h, g_Wout_h); cudaGetSymbolAddress(&p_Wout_l, g_Wout_l);
    cudaGetSymbolAddress(&p_Wff1_h, g_Wff1_h); cudaGetSymbolAddress(&p_Wff1_l, g_Wff1_l);
    cudaGetSymbolAddress(&p_Wff2_h, g_Wff2_h); cudaGetSymbolAddress(&p_Wff2_l, g_Wff2_l);
    cudaGetSymbolAddress(&p_cf, g_cf);         cudaGetSymbolAddress(&p_cb, g_cb);
    cudaGetSymbolAddress(&p_sinf, g_sinf);     cudaGetSymbolAddress(&p_sinb, g_sinb);

    cudaFuncSetAttribute(gemm_bf16x3_kernel<0>, cudaFuncAttributeMaxDynamicSharedMemorySize, GSMEM_BYTES);
    cudaFuncSetAttribute(gemm_bf16x3_kernel<1>, cudaFuncAttributeMaxDynamicSharedMemorySize, GSMEM_BYTES);
    cudaFuncSetAttribute(gemm_bf16x3_kernel<2>, cudaFuncAttributeMaxDynamicSharedMemorySize, GSMEM_BYTES);
    cudaFuncSetAttribute(gemm_bf16x3_kernel<3>, cudaFuncAttributeMaxDynamicSharedMemorySize, GSMEM_BYTES);
    cudaFuncSetAttribute(scan_p1_kernel, cudaFuncAttributeMaxDynamicSharedMemorySize, CCH*128*4);
    cudaFuncSetAttribute(scan_p3_kernel, cudaFuncAttributeMaxDynamicSharedMemorySize, 2*CCH*128*4);

    dim3 tb(32, 8);
    // weight prep: transpose + split
    transpose_split_kernel<<<dim3(HH/32, HH/32), tb>>>(W_in,  (__nv_bfloat16*)p_Wug_h, (__nv_bfloat16*)p_Wug_l, HH, HH);
    transpose_split_kernel<<<dim3(HH/32, HH/32), tb>>>(W_gate, (__nv_bfloat16*)p_Wug_h + (size_t)HH*HH,
                                                        (__nv_bfloat16*)p_Wug_l + (size_t)HH*HH, HH, HH);
    transpose_split_kernel<<<dim3(HH/32, HH/32), tb>>>(W_out, (__nv_bfloat16*)p_Wout_h, (__nv_bfloat16*)p_Wout_l, HH, HH);
    transpose_split_kernel<<<dim3(H2/32, HH/32), tb>>>(W_ff1, (__nv_bfloat16*)p_Wff1_h, (__nv_bfloat16*)p_Wff1_l, HH, H2);
    transpose_split_kernel<<<dim3(HH/32, H2/32), tb>>>(W_ff2, (__nv_bfloat16*)p_Wff2_h, (__nv_bfloat16*)p_Wff2_l, H2, HH);

    // LN1 -> hidden (split)
    ln_split_kernel<<<LL, 256>>>(x, ln1_w, ln1_b, (__nv_bfloat16*)p_hid_h, (__nv_bfloat16*)p_hid_l);

    // G1: fused u / gate GEMM (N = 2048)
    gemm_bf16x3_kernel<0><<<dim3(LL/128, H2/128), GTHREADS, GSMEM_BYTES>>>(
        (const __nv_bfloat16*)p_hid_h, (const __nv_bfloat16*)p_hid_l, HH,
        (const __nv_bfloat16*)p_Wug_h, (const __nv_bfloat16*)p_Wug_l,
        b_in, b_gate, nullptr, (float*)p_u, (float*)p_gate, nullptr, nullptr);

    // scan
    scan_p1_kernel<<<dim3(GG, HH/128), 128, CCH*128*4>>>(
        (const float*)p_u, sdecay, (float*)p_cf, (float*)p_cb);
    scan_p2_kernel<<<HH/256, 256>>>(
        (const float*)p_cf, (const float*)p_cb, sdecay, (float*)p_sinf, (float*)p_sinb);
    scan_p3_kernel<<<dim3(GG, HH/128), 128, 2*CCH*128*4>>>(
        (const float*)p_u, (const float*)p_gate, sdecay,
        (const float*)p_sinf, (const float*)p_sinb,
        (__nv_bfloat16*)p_st_h, (__nv_bfloat16*)p_st_l);

    // G2: y = x + state@W_out + b_out
    gemm_bf16x3_kernel<1><<<dim3(LL/128, HH/128), GTHREADS, GSMEM_BYTES>>>(
        (const __nv_bfloat16*)p_st_h, (const __nv_bfloat16*)p_st_l, HH,
        (const __nv_bfloat16*)p_Wout_h, (const __nv_bfloat16*)p_Wout_l,
        b_out, nullptr, x, (float*)p_y, nullptr, nullptr, nullptr);

    // LN2 -> h (split)
    ln_split_kernel<<<LL, 256>>>((const float*)p_y, ln2_w, ln2_b,
                                 (__nv_bfloat16*)p_h2_h, (__nv_bfloat16*)p_h2_l);

    // G3: ff1 = silu(h@W_ff1 + b_ff1), split for next GEMM (N = 2048)
    gemm_bf16x3_kernel<2><<<dim3(LL/128, H2/128), GTHREADS, GSMEM_BYTES>>>(
        (const __nv_bfloat16*)p_h2_h, (const __nv_bfloat16*)p_h2_l, HH,
        (const __nv_bfloat16*)p_Wff1_h, (const __nv_bfloat16*)p_Wff1_l,
        b_ff1, nullptr, nullptr, nullptr, nullptr,
        (__nv_bfloat16*)p_ff1_h, (__nv_bfloat16*)p_ff1_l);

    // G4: out = y + ff1@W_ff2 + b_ff2  (K = 2048)
    gemm_bf16x3_kernel<3><<<dim3(LL/128, HH/128), GTHREADS, GSMEM_BYTES>>>(
        (const __nv_bfloat16*)p_ff1_h, (const __nv_bfloat16*)p_ff1_l, H2,
        (const __nv_bfloat16*)p_Wff2_h, (const __nv_bfloat16*)p_Wff2_l,
        b_ff2, nullptr, (const float*)p_y, out, nullptr, nullptr, nullptr);
}